// round 16
// baseline (speedup 1.0000x reference)
#include <cuda_runtime.h>
#include <cuda_bf16.h>
#include <cstdint>

// Problem constants
#define Nn   8192
#define Kk   4
#define Bb   16
#define Dd   512
#define Mm   64
#define DP1  513
#define CAP  1024
#define NA   (Nn*Kk)   // 32768 assignments
#define CPAD 32        // counter padding: one 128B line per expert counter

// Scratch (device globals — no allocation allowed)
__device__ float g_inv[Mm*Bb];        // 1/col-norm per (expert, b)
__device__ int   g_cnt[Mm*CPAD];      // padded per-expert counters
__device__ int   g_list[Mm*CAP];      // assignment ids grouped by expert

typedef unsigned long long ull;

// ---- packed f32x2 helpers (sm_100+ PTX) ----
__device__ __forceinline__ ull pk2(float lo, float hi){
    ull v; asm("mov.b64 %0, {%1,%2};" : "=l"(v) : "f"(lo), "f"(hi)); return v;
}
__device__ __forceinline__ void unpk2(ull v, float& lo, float& hi){
    asm("mov.b64 {%0,%1}, %2;" : "=f"(lo), "=f"(hi) : "l"(v));
}
__device__ __forceinline__ void fma2(ull& d, ull a, ull b){
    asm("fma.rn.f32x2 %0, %1, %2, %0;" : "+l"(d) : "l"(a), "l"(b));
}
__device__ __forceinline__ void add2(ull& d, ull a){
    asm("add.rn.f32x2 %0, %0, %1;" : "+l"(d) : "l"(a));
}

// ---------------------------------------------------------------------------
// Kernel 1: column inverse norms (over all D+1 rows) + reset padded counters
// ---------------------------------------------------------------------------
__global__ void k_norm(const float* __restrict__ U){
    __shared__ float sm[256];
    const int m = blockIdx.x, t = threadIdx.x;
    const int b = t & 15, r0 = t >> 4;
    const float* Um = U + (size_t)m * DP1 * Bb;
    float s = 0.f;
    for (int d = r0; d < DP1; d += 16){
        float v = Um[d*Bb + b];
        s += v*v;
    }
    sm[t] = s;
    __syncthreads();
    if (t < 16){
        float tot = 0.f;
        #pragma unroll
        for (int i = 0; i < 16; i++) tot += sm[t + 16*i];
        float y = rsqrtf(tot);
        y = y * (1.5f - 0.5f*tot*y*y);   // one Newton step for accuracy
        g_inv[m*Bb + t] = y;
    }
    if (t == 0) g_cnt[m*CPAD] = 0;
}

// ---------------------------------------------------------------------------
// Kernel 2: counting scatter; padded counters -> 64 LTS slices in parallel
// ---------------------------------------------------------------------------
__global__ void k_build(const int* __restrict__ idx){
    int a = blockIdx.x * blockDim.x + threadIdx.x;
    if (a < NA){
        int e = idx[a] & 63;
        int pos = atomicAdd(&g_cnt[e*CPAD], 1);
        if (pos < CAP) g_list[e*CAP + pos] = a;
    }
}

// ---------------------------------------------------------------------------
// Kernel 3: writes pass (R12 atomic body + depth-2 h prefetch), S1=16:
// 1024 blocks, ~32 serial matches per block -> shorter dependent chains,
// ~7 blocks/SM for latency overlap.
// ---------------------------------------------------------------------------
#define S1 16
__global__ void __launch_bounds__(256) k_writes(const float* __restrict__ h,
                                                const float* __restrict__ U,
                                                float* __restrict__ out){
    const int e   = blockIdx.x >> 4;     // /S1
    const int sub = blockIdx.x & (S1-1);
    const int t   = threadIdx.x;
    const float* Ue = U + (size_t)e * DP1 * Bb;

    // Pre-scaled expert rows for d0=t, d1=t+256, packed as f32x2 pairs
    ull u0[8], u1[8];
    #pragma unroll
    for (int p = 0; p < 8; p++){
        float i0 = g_inv[e*Bb + 2*p];
        float i1 = g_inv[e*Bb + 2*p + 1];
        u0[p] = pk2(Ue[(size_t)t*Bb + 2*p]*i0,         Ue[(size_t)t*Bb + 2*p + 1]*i1);
        u1[p] = pk2(Ue[(size_t)(t+256)*Bb + 2*p]*i0,   Ue[(size_t)(t+256)*Bb + 2*p + 1]*i1);
    }

    int cnt = g_cnt[e*CPAD]; if (cnt > CAP) cnt = CAP;
    const int s    = (cnt * sub) / S1;
    const int epos = (cnt * (sub+1)) / S1;
    if (s >= epos) return;

    int a = g_list[e*CAP + s];
    const float4* hp = (const float4*)(h + (size_t)a * Bb);
    float4 A0 = __ldg(hp+0), A1 = __ldg(hp+1), A2 = __ldg(hp+2), A3 = __ldg(hp+3);

    for (int i = s; i < epos; i++){
        ull hh[8] = { pk2(A0.x,A0.y), pk2(A0.z,A0.w), pk2(A1.x,A1.y), pk2(A1.z,A1.w),
                      pk2(A2.x,A2.y), pk2(A2.z,A2.w), pk2(A3.x,A3.y), pk2(A3.z,A3.w) };
        int an = a;
        if (i + 1 < epos) an = g_list[e*CAP + i + 1];
        const float4* hn = (const float4*)(h + (size_t)an * Bb);
        float4 B0 = __ldg(hn+0), B1 = __ldg(hn+1), B2 = __ldg(hn+2), B3 = __ldg(hn+3);

        ull acc0 = 0ull, acc1 = 0ull;
        #pragma unroll
        for (int p = 0; p < 8; p++){
            fma2(acc0, u0[p], hh[p]);
            fma2(acc1, u1[p], hh[p]);
        }
        float x, y;
        unpk2(acc0, x, y); float r0 = x + y;
        unpk2(acc1, x, y); float r1 = x + y;
        float* w = out + (size_t)(a >> 2) * Dd;
        atomicAdd(w + t,       r0);   // RED (no return)
        atomicAdd(w + t + 256, r1);

        a = an; A0 = B0; A1 = B1; A2 = B2; A3 = B3;
    }
}

// ---------------------------------------------------------------------------
// Kernel 4: recon + loss (R15 WIN structure). Only change: j-loop unrolled
// x2 so 8 w-loads are batched per iteration (MLP 4 -> 8), halving the
// number of exposed L2-latency windows.
// ---------------------------------------------------------------------------
#define S2 4
__global__ void __launch_bounds__(256,2) k_recon(const float* __restrict__ h,
                                                 const float* __restrict__ U,
                                                 const float* __restrict__ w,
                                                 float* __restrict__ loss){
    __shared__ __align__(16) float Us[Dd*20];
    __shared__ float wred[8];
    const int e   = blockIdx.x >> 2;     // /S2
    const int sub = blockIdx.x & (S2-1);
    const float* Ue = U + (size_t)e * DP1 * Bb;

    // cooperative load + normalize into padded smem
    for (int i = threadIdx.x; i < Dd*Bb; i += 256){
        int d = i >> 4, b = i & 15;
        Us[d*20 + b] = Ue[i] * g_inv[e*Bb + b];
    }
    __syncthreads();

    int cnt = g_cnt[e*CPAD]; if (cnt > CAP) cnt = CAP;
    const int s    = (cnt * sub) / S2;
    const int epos = (cnt * (sub+1)) / S2;
    const int lane = threadIdx.x & 31;
    const int wid  = threadIdx.x >> 5;

    float lsum = 0.f;   // per-lane partial loss

    for (int g0 = s + wid*4; g0 < epos; g0 += 8*4){
        int a_[4]; float vm[4];
        #pragma unroll
        for (int mi = 0; mi < 4; mi++){
            int gi = g0 + mi;
            bool v = gi < epos;
            a_[mi] = g_list[e*CAP + (v ? gi : (epos-1))];
            vm[mi] = v ? 1.f : 0.f;
        }
        const float* w0 = w + (size_t)(a_[0] >> 2) * Dd;
        const float* w1 = w + (size_t)(a_[1] >> 2) * Dd;
        const float* w2 = w + (size_t)(a_[2] >> 2) * Dd;
        const float* w3 = w + (size_t)(a_[3] >> 2) * Dd;

        ull r2[32];   // flattened: v = m*8 + p
        #pragma unroll
        for (int p = 0; p < 32; p++) r2[p] = 0ull;

        #pragma unroll
        for (int j = 0; j < 16; j += 2){
            const int dA = lane + 32*j;
            const int dB = dA + 32;
            // batch all 8 loads first (MLP 8)
            float a0 = __ldg(w0 + dA), a1 = __ldg(w1 + dA);
            float a2 = __ldg(w2 + dA), a3 = __ldg(w3 + dA);
            float b0 = __ldg(w0 + dB), b1 = __ldg(w1 + dB);
            float b2 = __ldg(w2 + dB), b3 = __ldg(w3 + dB);

            {
                ull ww0 = pk2(a0, a0), ww1 = pk2(a1, a1);
                ull ww2 = pk2(a2, a2), ww3 = pk2(a3, a3);
                const float4* row = (const float4*)&Us[dA*20];
                #pragma unroll
                for (int bq = 0; bq < 4; bq++){
                    float4 u = row[bq];
                    ull uL = pk2(u.x, u.y), uH = pk2(u.z, u.w);
                    fma2(r2[2*bq],      ww0, uL); fma2(r2[2*bq+1],      ww0, uH);
                    fma2(r2[8+2*bq],    ww1, uL); fma2(r2[8+2*bq+1],    ww1, uH);
                    fma2(r2[16+2*bq],   ww2, uL); fma2(r2[16+2*bq+1],   ww2, uH);
                    fma2(r2[24+2*bq],   ww3, uL); fma2(r2[24+2*bq+1],   ww3, uH);
                }
            }
            {
                ull ww0 = pk2(b0, b0), ww1 = pk2(b1, b1);
                ull ww2 = pk2(b2, b2), ww3 = pk2(b3, b3);
                const float4* row = (const float4*)&Us[dB*20];
                #pragma unroll
                for (int bq = 0; bq < 4; bq++){
                    float4 u = row[bq];
                    ull uL = pk2(u.x, u.y), uH = pk2(u.z, u.w);
                    fma2(r2[2*bq],      ww0, uL); fma2(r2[2*bq+1],      ww0, uH);
                    fma2(r2[8+2*bq],    ww1, uL); fma2(r2[8+2*bq+1],    ww1, uH);
                    fma2(r2[16+2*bq],   ww2, uL); fma2(r2[16+2*bq+1],   ww2, uH);
                    fma2(r2[24+2*bq],   ww3, uL); fma2(r2[24+2*bq+1],   ww3, uH);
                }
            }
        }

        // register-halving tree: 32 ull/lane -> lane L holds full sum of v=L.
        #pragma unroll
        for (int o = 16; o >= 1; o >>= 1){
            const bool hb = (lane & o) != 0;
            #pragma unroll
            for (int i = 0; i < o; i++){
                ull send = hb ? r2[i]     : r2[i + o];
                ull keep = hb ? r2[i + o] : r2[i];
                ull recv = __shfl_xor_sync(0xffffffffu, send, o);
                add2(keep, recv);
                r2[i] = keep;
            }
        }

        // per-lane loss: lane owns (m = lane>>3, b = 2*(lane&7), +1)
        int   am  = a_[0]; float vmm = vm[0];
        if (lane >= 8)  { am = a_[1]; vmm = vm[1]; }
        if (lane >= 16) { am = a_[2]; vmm = vm[2]; }
        if (lane >= 24) { am = a_[3]; vmm = vm[3]; }
        const float2 hv = *(const float2*)(h + (size_t)am * Bb + 2*(lane & 7));
        float rl, rh; unpk2(r2[0], rl, rh);
        float e0 = rl - hv.x, e1 = rh - hv.y;
        lsum += vmm * (e0*e0 + e1*e1);
    }

    // one warp-wide loss reduce (outside the group loop)
    #pragma unroll
    for (int ofs = 16; ofs > 0; ofs >>= 1)
        lsum += __shfl_xor_sync(0xffffffffu, lsum, ofs);
    if (lane == 0) wred[wid] = lsum;
    __syncthreads();
    if (threadIdx.x == 0){
        float sblk = 0.f;
        #pragma unroll
        for (int i = 0; i < 8; i++) sblk += wred[i];
        atomicAdd(loss, sblk * (1.0f / (float)(Nn*Kk*Bb)));
    }
}

// ---------------------------------------------------------------------------
extern "C" void kernel_launch(void* const* d_in, const int* in_sizes, int n_in,
                              void* d_out, int out_size){
    const float* h   = (const float*)d_in[0];   // (N,K,B) f32
    const int*   idx = (const int*)  d_in[1];   // (N,K) i32
    const float* U   = (const float*)d_in[2];   // (M,D+1,B) f32

    float* out  = (float*)d_out;                // writes (N,D) then loss scalar
    float* loss = out + (out_size - 1);

    cudaMemsetAsync(d_out, 0, (size_t)out_size * sizeof(float));  // atomic targets need zeros
    k_norm  <<<Mm, 256>>>(U);
    k_build <<<NA/256, 256>>>(idx);
    k_writes<<<Mm*S1, 256>>>(h, U, out);
    k_recon <<<Mm*S2, 256>>>(h, U, out, loss);
}

// round 17
// speedup vs baseline: 1.1100x; 1.1100x over previous
#include <cuda_runtime.h>
#include <cuda_bf16.h>
#include <cstdint>

// Problem constants
#define Nn   8192
#define Kk   4
#define Bb   16
#define Dd   512
#define Mm   64
#define DP1  513
#define CAP  1024
#define NA   (Nn*Kk)   // 32768 assignments
#define CPAD 32        // counter padding: one 128B line per expert counter

// Scratch (device globals — no allocation allowed)
__device__ float g_inv[Mm*Bb];        // 1/col-norm per (expert, b)
__device__ int   g_cnt[Mm*CPAD];      // padded per-expert counters
__device__ int   g_list[Mm*CAP];      // assignment ids grouped by expert

typedef unsigned long long ull;

// ---- packed f32x2 helpers (sm_100+ PTX) ----
__device__ __forceinline__ ull pk2(float lo, float hi){
    ull v; asm("mov.b64 %0, {%1,%2};" : "=l"(v) : "f"(lo), "f"(hi)); return v;
}
__device__ __forceinline__ void unpk2(ull v, float& lo, float& hi){
    asm("mov.b64 {%0,%1}, %2;" : "=f"(lo), "=f"(hi) : "l"(v));
}
__device__ __forceinline__ void fma2(ull& d, ull a, ull b){
    asm("fma.rn.f32x2 %0, %1, %2, %0;" : "+l"(d) : "l"(a), "l"(b));
}
__device__ __forceinline__ void add2(ull& d, ull a){
    asm("add.rn.f32x2 %0, %0, %1;" : "+l"(d) : "l"(a));
}

// ---------------------------------------------------------------------------
// Kernel 1: column inverse norms (over all D+1 rows) + reset padded counters
// ---------------------------------------------------------------------------
__global__ void k_norm(const float* __restrict__ U){
    __shared__ float sm[256];
    const int m = blockIdx.x, t = threadIdx.x;
    const int b = t & 15, r0 = t >> 4;
    const float* Um = U + (size_t)m * DP1 * Bb;
    float s = 0.f;
    for (int d = r0; d < DP1; d += 16){
        float v = Um[d*Bb + b];
        s += v*v;
    }
    sm[t] = s;
    __syncthreads();
    if (t < 16){
        float tot = 0.f;
        #pragma unroll
        for (int i = 0; i < 16; i++) tot += sm[t + 16*i];
        float y = rsqrtf(tot);
        y = y * (1.5f - 0.5f*tot*y*y);   // one Newton step for accuracy
        g_inv[m*Bb + t] = y;
    }
    if (t == 0) g_cnt[m*CPAD] = 0;
}

// ---------------------------------------------------------------------------
// Kernel 2: counting scatter; padded counters -> 64 LTS slices in parallel
// ---------------------------------------------------------------------------
__global__ void k_build(const int* __restrict__ idx){
    int a = blockIdx.x * blockDim.x + threadIdx.x;
    if (a < NA){
        int e = idx[a] & 63;
        int pos = atomicAdd(&g_cnt[e*CPAD], 1);
        if (pos < CAP) g_list[e*CAP + pos] = a;
    }
}

// ---------------------------------------------------------------------------
// Kernel 3: writes pass, S1=8 (proven), atomics, but TWO matches per loop
// iteration: 32 independent fma2 + 4 REDs per iteration, pair-prefetched.
// ---------------------------------------------------------------------------
#define S1 8
__global__ void __launch_bounds__(256) k_writes(const float* __restrict__ h,
                                                const float* __restrict__ U,
                                                float* __restrict__ out){
    const int e   = blockIdx.x >> 3;     // /S1
    const int sub = blockIdx.x & (S1-1);
    const int t   = threadIdx.x;
    const float* Ue = U + (size_t)e * DP1 * Bb;

    // Pre-scaled expert rows for d0=t, d1=t+256, packed as f32x2 pairs
    ull u0[8], u1[8];
    #pragma unroll
    for (int p = 0; p < 8; p++){
        float i0 = g_inv[e*Bb + 2*p];
        float i1 = g_inv[e*Bb + 2*p + 1];
        u0[p] = pk2(Ue[(size_t)t*Bb + 2*p]*i0,         Ue[(size_t)t*Bb + 2*p + 1]*i1);
        u1[p] = pk2(Ue[(size_t)(t+256)*Bb + 2*p]*i0,   Ue[(size_t)(t+256)*Bb + 2*p + 1]*i1);
    }

    int cnt = g_cnt[e*CPAD]; if (cnt > CAP) cnt = CAP;
    const int s    = (cnt * sub) / S1;
    const int epos = (cnt * (sub+1)) / S1;
    if (s >= epos) return;

    // prologue: load entries s and s+1 (guarded)
    int aA = g_list[e*CAP + s];
    int aB = (s + 1 < epos) ? g_list[e*CAP + s + 1] : aA;
    const float4* hA = (const float4*)(h + (size_t)aA * Bb);
    const float4* hB = (const float4*)(h + (size_t)aB * Bb);
    float4 A0 = __ldg(hA+0), A1 = __ldg(hA+1), A2 = __ldg(hA+2), A3 = __ldg(hA+3);
    float4 B0 = __ldg(hB+0), B1 = __ldg(hB+1), B2 = __ldg(hB+2), B3 = __ldg(hB+3);

    int i = s;
    for (; i + 1 < epos; i += 2){
        // prefetch next pair (guarded)
        int aC = aB, aD = aB;
        if (i + 2 < epos) aC = g_list[e*CAP + i + 2];
        if (i + 3 < epos) aD = g_list[e*CAP + i + 3];
        const float4* hC = (const float4*)(h + (size_t)aC * Bb);
        const float4* hD = (const float4*)(h + (size_t)aD * Bb);
        float4 C0 = __ldg(hC+0), C1 = __ldg(hC+1), C2 = __ldg(hC+2), C3 = __ldg(hC+3);
        float4 D0 = __ldg(hD+0), D1 = __ldg(hD+1), D2 = __ldg(hD+2), D3 = __ldg(hD+3);

        // compute both current matches: 32 independent fma2 streams
        ull ha[8] = { pk2(A0.x,A0.y), pk2(A0.z,A0.w), pk2(A1.x,A1.y), pk2(A1.z,A1.w),
                      pk2(A2.x,A2.y), pk2(A2.z,A2.w), pk2(A3.x,A3.y), pk2(A3.z,A3.w) };
        ull hb[8] = { pk2(B0.x,B0.y), pk2(B0.z,B0.w), pk2(B1.x,B1.y), pk2(B1.z,B1.w),
                      pk2(B2.x,B2.y), pk2(B2.z,B2.w), pk2(B3.x,B3.y), pk2(B3.z,B3.w) };
        ull accA0 = 0ull, accA1 = 0ull, accB0 = 0ull, accB1 = 0ull;
        #pragma unroll
        for (int p = 0; p < 8; p++){
            fma2(accA0, u0[p], ha[p]);
            fma2(accA1, u1[p], ha[p]);
            fma2(accB0, u0[p], hb[p]);
            fma2(accB1, u1[p], hb[p]);
        }
        float x, y;
        unpk2(accA0, x, y); float rA0 = x + y;
        unpk2(accA1, x, y); float rA1 = x + y;
        unpk2(accB0, x, y); float rB0 = x + y;
        unpk2(accB1, x, y); float rB1 = x + y;
        float* wA = out + (size_t)(aA >> 2) * Dd;
        float* wB = out + (size_t)(aB >> 2) * Dd;
        atomicAdd(wA + t,       rA0);
        atomicAdd(wA + t + 256, rA1);
        atomicAdd(wB + t,       rB0);
        atomicAdd(wB + t + 256, rB1);

        aA = aC; aB = aD;
        A0 = C0; A1 = C1; A2 = C2; A3 = C3;
        B0 = D0; B1 = D1; B2 = D2; B3 = D3;
    }
    if (i < epos){   // odd tail: entry in A regs
        ull ha[8] = { pk2(A0.x,A0.y), pk2(A0.z,A0.w), pk2(A1.x,A1.y), pk2(A1.z,A1.w),
                      pk2(A2.x,A2.y), pk2(A2.z,A2.w), pk2(A3.x,A3.y), pk2(A3.z,A3.w) };
        ull acc0 = 0ull, acc1 = 0ull;
        #pragma unroll
        for (int p = 0; p < 8; p++){
            fma2(acc0, u0[p], ha[p]);
            fma2(acc1, u1[p], ha[p]);
        }
        float x, y;
        unpk2(acc0, x, y); float r0 = x + y;
        unpk2(acc1, x, y); float r1 = x + y;
        float* w = out + (size_t)(aA >> 2) * Dd;
        atomicAdd(w + t,       r0);
        atomicAdd(w + t + 256, r1);
    }
}

// ---------------------------------------------------------------------------
// Kernel 4: recon + loss — PROVEN R15 version (30.0us measured), unchanged.
// ---------------------------------------------------------------------------
#define S2 4
__global__ void __launch_bounds__(256,2) k_recon(const float* __restrict__ h,
                                                 const float* __restrict__ U,
                                                 const float* __restrict__ w,
                                                 float* __restrict__ loss){
    __shared__ __align__(16) float Us[Dd*20];
    __shared__ float wred[8];
    const int e   = blockIdx.x >> 2;     // /S2
    const int sub = blockIdx.x & (S2-1);
    const float* Ue = U + (size_t)e * DP1 * Bb;

    // cooperative load + normalize into padded smem
    for (int i = threadIdx.x; i < Dd*Bb; i += 256){
        int d = i >> 4, b = i & 15;
        Us[d*20 + b] = Ue[i] * g_inv[e*Bb + b];
    }
    __syncthreads();

    int cnt = g_cnt[e*CPAD]; if (cnt > CAP) cnt = CAP;
    const int s    = (cnt * sub) / S2;
    const int epos = (cnt * (sub+1)) / S2;
    const int lane = threadIdx.x & 31;
    const int wid  = threadIdx.x >> 5;

    float lsum = 0.f;   // per-lane partial loss

    for (int g0 = s + wid*4; g0 < epos; g0 += 8*4){
        int a_[4]; float vm[4];
        #pragma unroll
        for (int mi = 0; mi < 4; mi++){
            int gi = g0 + mi;
            bool v = gi < epos;
            a_[mi] = g_list[e*CAP + (v ? gi : (epos-1))];
            vm[mi] = v ? 1.f : 0.f;
        }
        const float* w0 = w + (size_t)(a_[0] >> 2) * Dd;
        const float* w1 = w + (size_t)(a_[1] >> 2) * Dd;
        const float* w2 = w + (size_t)(a_[2] >> 2) * Dd;
        const float* w3 = w + (size_t)(a_[3] >> 2) * Dd;

        ull r2[32];   // flattened: v = m*8 + p
        #pragma unroll
        for (int p = 0; p < 32; p++) r2[p] = 0ull;

        for (int j = 0; j < 16; j++){
            const int d = lane + 32*j;
            float wv0 = __ldg(w0 + d), wv1 = __ldg(w1 + d);
            float wv2 = __ldg(w2 + d), wv3 = __ldg(w3 + d);
            ull ww0 = pk2(wv0, wv0), ww1 = pk2(wv1, wv1);
            ull ww2 = pk2(wv2, wv2), ww3 = pk2(wv3, wv3);
            const float4* row = (const float4*)&Us[d*20];
            #pragma unroll
            for (int bq = 0; bq < 4; bq++){
                float4 u = row[bq];
                ull uL = pk2(u.x, u.y), uH = pk2(u.z, u.w);
                fma2(r2[2*bq],      ww0, uL); fma2(r2[2*bq+1],      ww0, uH);
                fma2(r2[8+2*bq],    ww1, uL); fma2(r2[8+2*bq+1],    ww1, uH);
                fma2(r2[16+2*bq],   ww2, uL); fma2(r2[16+2*bq+1],   ww2, uH);
                fma2(r2[24+2*bq],   ww3, uL); fma2(r2[24+2*bq+1],   ww3, uH);
            }
        }

        // register-halving tree: 32 ull/lane -> lane L holds full sum of v=L.
        #pragma unroll
        for (int o = 16; o >= 1; o >>= 1){
            const bool hb = (lane & o) != 0;
            #pragma unroll
            for (int i = 0; i < o; i++){
                ull send = hb ? r2[i]     : r2[i + o];
                ull keep = hb ? r2[i + o] : r2[i];
                ull recv = __shfl_xor_sync(0xffffffffu, send, o);
                add2(keep, recv);
                r2[i] = keep;
            }
        }

        // per-lane loss: lane owns (m = lane>>3, b = 2*(lane&7), +1)
        int   am  = a_[0]; float vmm = vm[0];
        if (lane >= 8)  { am = a_[1]; vmm = vm[1]; }
        if (lane >= 16) { am = a_[2]; vmm = vm[2]; }
        if (lane >= 24) { am = a_[3]; vmm = vm[3]; }
        const float2 hv = *(const float2*)(h + (size_t)am * Bb + 2*(lane & 7));
        float rl, rh; unpk2(r2[0], rl, rh);
        float e0 = rl - hv.x, e1 = rh - hv.y;
        lsum += vmm * (e0*e0 + e1*e1);
    }

    // one warp-wide loss reduce (outside the group loop)
    #pragma unroll
    for (int ofs = 16; ofs > 0; ofs >>= 1)
        lsum += __shfl_xor_sync(0xffffffffu, lsum, ofs);
    if (lane == 0) wred[wid] = lsum;
    __syncthreads();
    if (threadIdx.x == 0){
        float sblk = 0.f;
        #pragma unroll
        for (int i = 0; i < 8; i++) sblk += wred[i];
        atomicAdd(loss, sblk * (1.0f / (float)(Nn*Kk*Bb)));
    }
}

// ---------------------------------------------------------------------------
extern "C" void kernel_launch(void* const* d_in, const int* in_sizes, int n_in,
                              void* d_out, int out_size){
    const float* h   = (const float*)d_in[0];   // (N,K,B) f32
    const int*   idx = (const int*)  d_in[1];   // (N,K) i32
    const float* U   = (const float*)d_in[2];   // (M,D+1,B) f32

    float* out  = (float*)d_out;                // writes (N,D) then loss scalar
    float* loss = out + (out_size - 1);

    cudaMemsetAsync(d_out, 0, (size_t)out_size * sizeof(float));  // atomic targets need zeros
    k_norm  <<<Mm, 256>>>(U);
    k_build <<<NA/256, 256>>>(idx);
    k_writes<<<Mm*S1, 256>>>(h, U, out);
    k_recon <<<Mm*S2, 256>>>(h, U, out, loss);
}